// round 3
// baseline (speedup 1.0000x reference)
#include <cuda_runtime.h>
#include <math.h>

#define D_DIM 64
#define SPLIT 16
#define MAXB  64
#define ROWS_C 512

// Scratch (no device allocs allowed): per-(batch,split) partial softmax state + final attn row.
__device__ float g_part_m[MAXB * SPLIT];
__device__ float g_part_s[MAXB * SPLIT];
__device__ float g_part_acc[MAXB * SPLIT * D_DIM];
__device__ float g_attn[MAXB * D_DIM];

// ---------------------------------------------------------------------------
// Kernel A: per (batch, split) — compute logits, online softmax, partial attn
// accumulation. 256 threads = 8 warps; each warp processes 4 rows per iter.
// Lane owns elements [2*lane, 2*lane+1] of the D=64 vectors.
// ---------------------------------------------------------------------------
__global__ __launch_bounds__(256) void collect_kernel(
    const float* __restrict__ q, const float* __restrict__ kc,
    const float* __restrict__ v, const float* __restrict__ tcp,
    float* __restrict__ logits, int L)
{
    const int b    = blockIdx.x;
    const int sp   = blockIdx.y;
    const int rows = L / SPLIT;           // 512
    const int l0   = sp * rows;
    const int warp = threadIdx.x >> 5;
    const int lane = threadIdx.x & 31;

    const float inv_tc = __frcp_rn(tcp[0]);
    const float2 q2 = ((const float2*)(q + b * D_DIM))[lane];

    const float* kcb = kc + ((size_t)b * L + l0) * D_DIM;
    const float* vb  = v  + ((size_t)b * L + l0) * D_DIM;
    float*       lgb = logits + (size_t)b * L + l0;

    float m = -1e30f, s = 0.0f;
    float accx = 0.0f, accy = 0.0f;

    for (int i0 = warp * 4; i0 < rows; i0 += 32) {
        // Issue all 8 loads up front for MLP.
        float2 k0 = *(const float2*)(kcb + (i0 + 0) * D_DIM + 2 * lane);
        float2 k1 = *(const float2*)(kcb + (i0 + 1) * D_DIM + 2 * lane);
        float2 k2 = *(const float2*)(kcb + (i0 + 2) * D_DIM + 2 * lane);
        float2 k3 = *(const float2*)(kcb + (i0 + 3) * D_DIM + 2 * lane);
        float2 v0 = *(const float2*)(vb  + (i0 + 0) * D_DIM + 2 * lane);
        float2 v1 = *(const float2*)(vb  + (i0 + 1) * D_DIM + 2 * lane);
        float2 v2 = *(const float2*)(vb  + (i0 + 2) * D_DIM + 2 * lane);
        float2 v3 = *(const float2*)(vb  + (i0 + 3) * D_DIM + 2 * lane);

        float d0 = k0.x * q2.x + k0.y * q2.y;
        float d1 = k1.x * q2.x + k1.y * q2.y;
        float d2 = k2.x * q2.x + k2.y * q2.y;
        float d3 = k3.x * q2.x + k3.y * q2.y;

        #pragma unroll
        for (int off = 16; off; off >>= 1) {
            d0 += __shfl_xor_sync(0xffffffffu, d0, off);
            d1 += __shfl_xor_sync(0xffffffffu, d1, off);
            d2 += __shfl_xor_sync(0xffffffffu, d2, off);
            d3 += __shfl_xor_sync(0xffffffffu, d3, off);
        }
        d0 *= inv_tc; d1 *= inv_tc; d2 *= inv_tc; d3 *= inv_tc;

        if (lane == 0)
            *(float4*)(lgb + i0) = make_float4(d0, d1, d2, d3);

        // Online softmax update.
        float mx    = fmaxf(fmaxf(d0, d1), fmaxf(d2, d3));
        float m_new = fmaxf(m, mx);
        float c  = __expf(m - m_new);
        float p0 = __expf(d0 - m_new);
        float p1 = __expf(d1 - m_new);
        float p2 = __expf(d2 - m_new);
        float p3 = __expf(d3 - m_new);
        s    = s * c + (p0 + p1) + (p2 + p3);
        accx = accx * c + p0 * v0.x + p1 * v1.x + p2 * v2.x + p3 * v3.x;
        accy = accy * c + p0 * v0.y + p1 * v1.y + p2 * v2.y + p3 * v3.y;
        m = m_new;
    }

    // Combine the 8 warps of this block.
    __shared__ float sm_m[8];
    __shared__ float sm_s[8];
    __shared__ float sm_acc[8][D_DIM];

    sm_acc[warp][2 * lane]     = accx;
    sm_acc[warp][2 * lane + 1] = accy;
    if (lane == 0) { sm_m[warp] = m; sm_s[warp] = s; }
    __syncthreads();

    int t = threadIdx.x;
    if (t < D_DIM) {
        float M = sm_m[0];
        #pragma unroll
        for (int w = 1; w < 8; w++) M = fmaxf(M, sm_m[w]);
        float S = 0.0f, A = 0.0f;
        #pragma unroll
        for (int w = 0; w < 8; w++) {
            float e = __expf(sm_m[w] - M);
            S += sm_s[w] * e;
            A += sm_acc[w][t] * e;
        }
        int idx = b * SPLIT + sp;
        g_part_acc[idx * D_DIM + t] = A;
        if (t == 0) { g_part_m[idx] = M; g_part_s[idx] = S; }
    }
}

// ---------------------------------------------------------------------------
// Kernel B: merge the SPLIT partials per batch -> normalized attn[b][64].
// ---------------------------------------------------------------------------
__global__ __launch_bounds__(64) void reduce_kernel()
{
    int b = blockIdx.x;
    int d = threadIdx.x;  // 64 threads
    float M = -1e30f;
    #pragma unroll
    for (int j = 0; j < SPLIT; j++)
        M = fmaxf(M, g_part_m[b * SPLIT + j]);
    float S = 0.0f, A = 0.0f;
    #pragma unroll
    for (int j = 0; j < SPLIT; j++) {
        float e = __expf(g_part_m[b * SPLIT + j] - M);
        S += g_part_s[b * SPLIT + j] * e;
        A += g_part_acc[(b * SPLIT + j) * D_DIM + d] * e;
    }
    g_attn[b * D_DIM + d] = A / S;
}

// ---------------------------------------------------------------------------
// Kernel C: per row, gate = sigmoid(dot(kd,q)/td); out = gate * attn[b].
// ---------------------------------------------------------------------------
__global__ __launch_bounds__(256) void diffuse_kernel(
    const float* __restrict__ q, const float* __restrict__ kd,
    const float* __restrict__ tdp, float* __restrict__ out, int L)
{
    const int b    = blockIdx.x;
    const int l0   = blockIdx.y * ROWS_C;
    const int warp = threadIdx.x >> 5;
    const int lane = threadIdx.x & 31;

    const float inv_td = __frcp_rn(tdp[0]);
    const float2 q2 = ((const float2*)(q + b * D_DIM))[lane];
    const float2 a2 = ((const float2*)(g_attn + b * D_DIM))[lane];

    const float* kdb = kd  + ((size_t)b * L + l0) * D_DIM;
    float*       ob  = out + ((size_t)b * L + l0) * D_DIM;

    for (int i0 = warp * 4; i0 < ROWS_C; i0 += 32) {
        float2 k0 = *(const float2*)(kdb + (i0 + 0) * D_DIM + 2 * lane);
        float2 k1 = *(const float2*)(kdb + (i0 + 1) * D_DIM + 2 * lane);
        float2 k2 = *(const float2*)(kdb + (i0 + 2) * D_DIM + 2 * lane);
        float2 k3 = *(const float2*)(kdb + (i0 + 3) * D_DIM + 2 * lane);

        float d0 = k0.x * q2.x + k0.y * q2.y;
        float d1 = k1.x * q2.x + k1.y * q2.y;
        float d2 = k2.x * q2.x + k2.y * q2.y;
        float d3 = k3.x * q2.x + k3.y * q2.y;

        #pragma unroll
        for (int off = 16; off; off >>= 1) {
            d0 += __shfl_xor_sync(0xffffffffu, d0, off);
            d1 += __shfl_xor_sync(0xffffffffu, d1, off);
            d2 += __shfl_xor_sync(0xffffffffu, d2, off);
            d3 += __shfl_xor_sync(0xffffffffu, d3, off);
        }

        float g0 = __frcp_rn(1.0f + __expf(-d0 * inv_td));
        float g1 = __frcp_rn(1.0f + __expf(-d1 * inv_td));
        float g2 = __frcp_rn(1.0f + __expf(-d2 * inv_td));
        float g3 = __frcp_rn(1.0f + __expf(-d3 * inv_td));

        *(float2*)(ob + (i0 + 0) * D_DIM + 2 * lane) = make_float2(g0 * a2.x, g0 * a2.y);
        *(float2*)(ob + (i0 + 1) * D_DIM + 2 * lane) = make_float2(g1 * a2.x, g1 * a2.y);
        *(float2*)(ob + (i0 + 2) * D_DIM + 2 * lane) = make_float2(g2 * a2.x, g2 * a2.y);
        *(float2*)(ob + (i0 + 3) * D_DIM + 2 * lane) = make_float2(g3 * a2.x, g3 * a2.y);
    }
}

// ---------------------------------------------------------------------------
// Launch: inputs in metadata order: q, kc, kd, v, tc, td.
// d_out layout (tuple order): output [B,L,D] then logits [B,L].
// ---------------------------------------------------------------------------
extern "C" void kernel_launch(void* const* d_in, const int* in_sizes, int n_in,
                              void* d_out, int out_size)
{
    const float* q  = (const float*)d_in[0];
    const float* kc = (const float*)d_in[1];
    const float* kd = (const float*)d_in[2];
    const float* v  = (const float*)d_in[3];
    const float* tc = (const float*)d_in[4];
    const float* td = (const float*)d_in[5];

    int B = in_sizes[0] / D_DIM;           // q is [B,1,D]
    int L = in_sizes[1] / (B * D_DIM);     // kc is [B,L,D]

    float* out    = (float*)d_out;
    float* logits = out + (size_t)B * L * D_DIM;

    collect_kernel<<<dim3(B, SPLIT), 256>>>(q, kc, v, tc, logits, L);
    reduce_kernel<<<B, D_DIM>>>();
    diffuse_kernel<<<dim3(B, L / ROWS_C), 256>>>(q, kd, td, out, L);
}

// round 4
// speedup vs baseline: 1.0394x; 1.0394x over previous
#include <cuda_runtime.h>
#include <math.h>

#define D_DIM 64
#define SPLIT 64          // collect: 4096 CTAs x 128 rows (tail-fix: was 16 x 512)
#define MAXB  64
#define ROWS_C 128        // diffuse: 4096 CTAs (tail-fix: was 512 -> 1024 CTAs)

// Scratch (no device allocs allowed): per-(batch,split) partial softmax state + final attn row.
__device__ float g_part_m[MAXB * SPLIT];
__device__ float g_part_s[MAXB * SPLIT];
__device__ float g_part_acc[MAXB * SPLIT * D_DIM];
__device__ float g_attn[MAXB * D_DIM];

// ---------------------------------------------------------------------------
// Kernel A: per (batch, split) — compute logits, online softmax, partial attn
// accumulation. 256 threads = 8 warps; each warp processes 4 rows per iter.
// Lane owns elements [2*lane, 2*lane+1] of the D=64 vectors.
// ---------------------------------------------------------------------------
__global__ __launch_bounds__(256) void collect_kernel(
    const float* __restrict__ q, const float* __restrict__ kc,
    const float* __restrict__ v, const float* __restrict__ tcp,
    float* __restrict__ logits, int L)
{
    const int b    = blockIdx.x;
    const int sp   = blockIdx.y;
    const int rows = L / SPLIT;           // 128
    const int l0   = sp * rows;
    const int warp = threadIdx.x >> 5;
    const int lane = threadIdx.x & 31;

    const float inv_tc = __frcp_rn(tcp[0]);
    const float2 q2 = ((const float2*)(q + b * D_DIM))[lane];

    const float* kcb = kc + ((size_t)b * L + l0) * D_DIM;
    const float* vb  = v  + ((size_t)b * L + l0) * D_DIM;
    float*       lgb = logits + (size_t)b * L + l0;

    float m = -1e30f, s = 0.0f;
    float accx = 0.0f, accy = 0.0f;

    for (int i0 = warp * 4; i0 < rows; i0 += 32) {
        // Issue all 8 loads up front for MLP.
        float2 k0 = *(const float2*)(kcb + (i0 + 0) * D_DIM + 2 * lane);
        float2 k1 = *(const float2*)(kcb + (i0 + 1) * D_DIM + 2 * lane);
        float2 k2 = *(const float2*)(kcb + (i0 + 2) * D_DIM + 2 * lane);
        float2 k3 = *(const float2*)(kcb + (i0 + 3) * D_DIM + 2 * lane);
        float2 v0 = *(const float2*)(vb  + (i0 + 0) * D_DIM + 2 * lane);
        float2 v1 = *(const float2*)(vb  + (i0 + 1) * D_DIM + 2 * lane);
        float2 v2 = *(const float2*)(vb  + (i0 + 2) * D_DIM + 2 * lane);
        float2 v3 = *(const float2*)(vb  + (i0 + 3) * D_DIM + 2 * lane);

        float d0 = k0.x * q2.x + k0.y * q2.y;
        float d1 = k1.x * q2.x + k1.y * q2.y;
        float d2 = k2.x * q2.x + k2.y * q2.y;
        float d3 = k3.x * q2.x + k3.y * q2.y;

        #pragma unroll
        for (int off = 16; off; off >>= 1) {
            d0 += __shfl_xor_sync(0xffffffffu, d0, off);
            d1 += __shfl_xor_sync(0xffffffffu, d1, off);
            d2 += __shfl_xor_sync(0xffffffffu, d2, off);
            d3 += __shfl_xor_sync(0xffffffffu, d3, off);
        }
        d0 *= inv_tc; d1 *= inv_tc; d2 *= inv_tc; d3 *= inv_tc;

        if (lane == 0)
            *(float4*)(lgb + i0) = make_float4(d0, d1, d2, d3);

        // Online softmax update.
        float mx    = fmaxf(fmaxf(d0, d1), fmaxf(d2, d3));
        float m_new = fmaxf(m, mx);
        float c  = __expf(m - m_new);
        float p0 = __expf(d0 - m_new);
        float p1 = __expf(d1 - m_new);
        float p2 = __expf(d2 - m_new);
        float p3 = __expf(d3 - m_new);
        s    = s * c + (p0 + p1) + (p2 + p3);
        accx = accx * c + p0 * v0.x + p1 * v1.x + p2 * v2.x + p3 * v3.x;
        accy = accy * c + p0 * v0.y + p1 * v1.y + p2 * v2.y + p3 * v3.y;
        m = m_new;
    }

    // Combine the 8 warps of this block.
    __shared__ float sm_m[8];
    __shared__ float sm_s[8];
    __shared__ float sm_acc[8][D_DIM];

    sm_acc[warp][2 * lane]     = accx;
    sm_acc[warp][2 * lane + 1] = accy;
    if (lane == 0) { sm_m[warp] = m; sm_s[warp] = s; }
    __syncthreads();

    int t = threadIdx.x;
    if (t < D_DIM) {
        float M = sm_m[0];
        #pragma unroll
        for (int w = 1; w < 8; w++) M = fmaxf(M, sm_m[w]);
        float S = 0.0f, A = 0.0f;
        #pragma unroll
        for (int w = 0; w < 8; w++) {
            float e = __expf(sm_m[w] - M);
            S += sm_s[w] * e;
            A += sm_acc[w][t] * e;
        }
        int idx = b * SPLIT + sp;
        g_part_acc[idx * D_DIM + t] = A;
        if (t == 0) { g_part_m[idx] = M; g_part_s[idx] = S; }
    }
}

// ---------------------------------------------------------------------------
// Kernel B: merge the SPLIT partials per batch -> normalized attn[b][64].
// ---------------------------------------------------------------------------
__global__ __launch_bounds__(64) void reduce_kernel()
{
    int b = blockIdx.x;
    int d = threadIdx.x;  // 64 threads
    float M = -1e30f;
    #pragma unroll 8
    for (int j = 0; j < SPLIT; j++)
        M = fmaxf(M, g_part_m[b * SPLIT + j]);
    float S = 0.0f, A = 0.0f;
    #pragma unroll 8
    for (int j = 0; j < SPLIT; j++) {
        float e = __expf(g_part_m[b * SPLIT + j] - M);
        S += g_part_s[b * SPLIT + j] * e;
        A += g_part_acc[(b * SPLIT + j) * D_DIM + d] * e;
    }
    g_attn[b * D_DIM + d] = A / S;
}

// ---------------------------------------------------------------------------
// Kernel C: per row, gate = sigmoid(dot(kd,q)/td); out = gate * attn[b].
// ---------------------------------------------------------------------------
__global__ __launch_bounds__(256) void diffuse_kernel(
    const float* __restrict__ q, const float* __restrict__ kd,
    const float* __restrict__ tdp, float* __restrict__ out, int L)
{
    const int b    = blockIdx.x;
    const int l0   = blockIdx.y * ROWS_C;
    const int warp = threadIdx.x >> 5;
    const int lane = threadIdx.x & 31;

    const float inv_td = __frcp_rn(tdp[0]);
    const float2 q2 = ((const float2*)(q + b * D_DIM))[lane];
    const float2 a2 = ((const float2*)(g_attn + b * D_DIM))[lane];

    const float* kdb = kd  + ((size_t)b * L + l0) * D_DIM;
    float*       ob  = out + ((size_t)b * L + l0) * D_DIM;

    for (int i0 = warp * 4; i0 < ROWS_C; i0 += 32) {
        float2 k0 = *(const float2*)(kdb + (i0 + 0) * D_DIM + 2 * lane);
        float2 k1 = *(const float2*)(kdb + (i0 + 1) * D_DIM + 2 * lane);
        float2 k2 = *(const float2*)(kdb + (i0 + 2) * D_DIM + 2 * lane);
        float2 k3 = *(const float2*)(kdb + (i0 + 3) * D_DIM + 2 * lane);

        float d0 = k0.x * q2.x + k0.y * q2.y;
        float d1 = k1.x * q2.x + k1.y * q2.y;
        float d2 = k2.x * q2.x + k2.y * q2.y;
        float d3 = k3.x * q2.x + k3.y * q2.y;

        #pragma unroll
        for (int off = 16; off; off >>= 1) {
            d0 += __shfl_xor_sync(0xffffffffu, d0, off);
            d1 += __shfl_xor_sync(0xffffffffu, d1, off);
            d2 += __shfl_xor_sync(0xffffffffu, d2, off);
            d3 += __shfl_xor_sync(0xffffffffu, d3, off);
        }

        float g0 = __frcp_rn(1.0f + __expf(-d0 * inv_td));
        float g1 = __frcp_rn(1.0f + __expf(-d1 * inv_td));
        float g2 = __frcp_rn(1.0f + __expf(-d2 * inv_td));
        float g3 = __frcp_rn(1.0f + __expf(-d3 * inv_td));

        *(float2*)(ob + (i0 + 0) * D_DIM + 2 * lane) = make_float2(g0 * a2.x, g0 * a2.y);
        *(float2*)(ob + (i0 + 1) * D_DIM + 2 * lane) = make_float2(g1 * a2.x, g1 * a2.y);
        *(float2*)(ob + (i0 + 2) * D_DIM + 2 * lane) = make_float2(g2 * a2.x, g2 * a2.y);
        *(float2*)(ob + (i0 + 3) * D_DIM + 2 * lane) = make_float2(g3 * a2.x, g3 * a2.y);
    }
}

// ---------------------------------------------------------------------------
// Launch: inputs in metadata order: q, kc, kd, v, tc, td.
// d_out layout (tuple order): output [B,L,D] then logits [B,L].
// ---------------------------------------------------------------------------
extern "C" void kernel_launch(void* const* d_in, const int* in_sizes, int n_in,
                              void* d_out, int out_size)
{
    const float* q  = (const float*)d_in[0];
    const float* kc = (const float*)d_in[1];
    const float* kd = (const float*)d_in[2];
    const float* v  = (const float*)d_in[3];
    const float* tc = (const float*)d_in[4];
    const float* td = (const float*)d_in[5];

    int B = in_sizes[0] / D_DIM;           // q is [B,1,D]
    int L = in_sizes[1] / (B * D_DIM);     // kc is [B,L,D]

    float* out    = (float*)d_out;
    float* logits = out + (size_t)B * L * D_DIM;

    collect_kernel<<<dim3(B, SPLIT), 256>>>(q, kc, v, tc, logits, L);
    reduce_kernel<<<B, D_DIM>>>();
    diffuse_kernel<<<dim3(B, L / ROWS_C), 256>>>(q, kd, td, out, L);
}